// round 1
// baseline (speedup 1.0000x reference)
#include <cuda_runtime.h>
#include <math.h>

#define N_FFT   16384
#define L_SIG   8192
#define D_DIM   1024
#define BSZ     4
#define THREADS 512
#define NSTAGES 7   /* radix-4: 4^7 = 16384 */

// Scratch (allocation-free rule: __device__ globals)
__device__ float2 d_tw[N_FFT / 4];           // exp(-2*pi*i*k/N), k < N/4  (32 KB)
__device__ float2 d_Hf[(size_t)D_DIM * N_FFT]; // digit-reversed spectra of h rows (128 MB)

__device__ __forceinline__ float2 cmul(float2 a, float2 b) {
    return make_float2(a.x * b.x - a.y * b.y, a.x * b.y + a.y * b.x);
}

__global__ void twiddle_kernel() {
    int k = blockIdx.x * blockDim.x + threadIdx.x;
    if (k < N_FFT / 4) {
        double ang = -2.0 * 3.14159265358979323846 * (double)k / (double)N_FFT;
        d_tw[k] = make_float2((float)cos(ang), (float)sin(ang));
    }
}

// ---------------- radix-4 DIF forward: natural in -> base-4 digit-reversed out
__device__ __forceinline__ void fft_fwd(float2* s) {
    const int tid = threadIdx.x;
#pragma unroll
    for (int stage = 0; stage < NSTAGES; ++stage) {
        const int lq  = 12 - 2 * stage;       // log2(q), q = m/4, m = N >> 2*stage
        const int q   = 1 << lq;
        const int tws = 1 << (2 * stage);     // N/m
#pragma unroll
        for (int t = tid; t < (N_FFT >> 2); t += THREADS) {
            const int j    = t & (q - 1);
            const int base = (t >> lq) << (lq + 2);
            const int i0   = base + j;
            float2 a0 = s[i0], a1 = s[i0 + q], a2 = s[i0 + 2 * q], a3 = s[i0 + 3 * q];
            float2 t0 = make_float2(a0.x + a2.x, a0.y + a2.y);
            float2 t1 = make_float2(a0.x - a2.x, a0.y - a2.y);
            float2 t2 = make_float2(a1.x + a3.x, a1.y + a3.y);
            float2 t3 = make_float2(a1.x - a3.x, a1.y - a3.y);
            float2 b0 = make_float2(t0.x + t2.x, t0.y + t2.y);
            float2 b2 = make_float2(t0.x - t2.x, t0.y - t2.y);
            float2 b1 = make_float2(t1.x + t3.y, t1.y - t3.x);   // t1 - i*t3
            float2 b3 = make_float2(t1.x - t3.y, t1.y + t3.x);   // t1 + i*t3
            float2 w1 = d_tw[j * tws];
            float2 w2 = cmul(w1, w1);
            float2 w3 = cmul(w1, w2);
            s[i0]         = b0;
            s[i0 + q]     = cmul(b1, w1);
            s[i0 + 2 * q] = cmul(b2, w2);
            s[i0 + 3 * q] = cmul(b3, w3);
        }
        __syncthreads();
    }
}

// ---------------- radix-4 DIT inverse (conjugate-transpose of fft_fwd), no 1/N scale
__device__ __forceinline__ void fft_inv(float2* s) {
    const int tid = threadIdx.x;
#pragma unroll
    for (int stage = 0; stage < NSTAGES; ++stage) {
        const int lq  = 2 * stage;            // q = 4^stage, m = 4^(stage+1)
        const int q   = 1 << lq;
        const int tws = N_FFT >> (lq + 2);    // N/m
#pragma unroll
        for (int t = tid; t < (N_FFT >> 2); t += THREADS) {
            const int j    = t & (q - 1);
            const int base = (t >> lq) << (lq + 2);
            const int i0   = base + j;
            float2 c0 = s[i0], c1 = s[i0 + q], c2 = s[i0 + 2 * q], c3 = s[i0 + 3 * q];
            float2 w1 = d_tw[j * tws];
            w1.y = -w1.y;                     // conjugate for inverse
            float2 w2 = cmul(w1, w1);
            float2 w3 = cmul(w1, w2);
            float2 a1 = cmul(c1, w1);
            float2 a2 = cmul(c2, w2);
            float2 a3 = cmul(c3, w3);
            float2 u0 = make_float2(c0.x + a2.x, c0.y + a2.y);
            float2 u1 = make_float2(c0.x - a2.x, c0.y - a2.y);
            float2 u2 = make_float2(a1.x + a3.x, a1.y + a3.y);
            float2 u3 = make_float2(a1.x - a3.x, a1.y - a3.y);
            s[i0]         = make_float2(u0.x + u2.x, u0.y + u2.y);
            s[i0 + q]     = make_float2(u1.x - u3.y, u1.y + u3.x);  // u1 + i*u3
            s[i0 + 2 * q] = make_float2(u0.x - u2.x, u0.y - u2.y);
            s[i0 + 3 * q] = make_float2(u1.x + u3.y, u1.y - u3.x);  // u1 - i*u3
        }
        __syncthreads();
    }
}

// ---------------- per-row spectrum of h (recomputed every launch: determinism)
__global__ __launch_bounds__(THREADS, 1) void hfft_kernel(const float* __restrict__ h) {
    extern __shared__ float2 s[];
    const int d = blockIdx.x;
    const float* hr = h + (size_t)d * L_SIG;
    for (int i = threadIdx.x; i < L_SIG; i += THREADS)
        s[i] = make_float2(hr[i], 0.f);
    for (int i = L_SIG + threadIdx.x; i < N_FFT; i += THREADS)
        s[i] = make_float2(0.f, 0.f);
    __syncthreads();
    fft_fwd(s);
    float2* out = d_Hf + (size_t)d * N_FFT;
    for (int i = threadIdx.x; i < N_FFT; i += THREADS)
        out[i] = s[i];
}

// ---------------- FFT conv: one CTA per (d, b) row, d-major so batch-siblings share Hf in L2
__global__ __launch_bounds__(THREADS, 1) void conv_kernel(const float* __restrict__ x,
                                                          const float* __restrict__ Bp,
                                                          float* __restrict__ y) {
    extern __shared__ float2 s[];
    const int blk = blockIdx.x;
    const int d = blk >> 2;
    const int b = blk & 3;
    const float* xr = x + ((size_t)b * D_DIM + d) * L_SIG;
    float* yr       = y + ((size_t)b * D_DIM + d) * L_SIG;

    for (int i = threadIdx.x; i < L_SIG; i += THREADS)
        s[i] = make_float2(xr[i], 0.f);
    for (int i = L_SIG + threadIdx.x; i < N_FFT; i += THREADS)
        s[i] = make_float2(0.f, 0.f);
    __syncthreads();

    fft_fwd(s);

    const float2* Hr = d_Hf + (size_t)d * N_FFT;
    const float scale = 1.0f / (float)N_FFT;
    for (int i = threadIdx.x; i < N_FFT; i += THREADS) {
        float2 p = cmul(s[i], Hr[i]);
        s[i] = make_float2(p.x * scale, p.y * scale);
    }
    __syncthreads();

    fft_inv(s);

    const float Bv = Bp[d];
    for (int i = threadIdx.x; i < L_SIG; i += THREADS)
        yr[i] = s[i].x + Bv * xr[i];
}

extern "C" void kernel_launch(void* const* d_in, const int* in_sizes, int n_in,
                              void* d_out, int out_size) {
    const float* h = (const float*)d_in[0];
    const float* x = (const float*)d_in[1];
    const float* B = (const float*)d_in[2];
    float* y = (float*)d_out;

    const size_t smem = (size_t)N_FFT * sizeof(float2);  // 128 KB
    // Idempotent; persists after first (uncaptured) correctness call.
    cudaFuncSetAttribute(hfft_kernel, cudaFuncAttributeMaxDynamicSharedMemorySize, (int)smem);
    cudaFuncSetAttribute(conv_kernel, cudaFuncAttributeMaxDynamicSharedMemorySize, (int)smem);

    twiddle_kernel<<<(N_FFT / 4 + 255) / 256, 256>>>();
    hfft_kernel<<<D_DIM, THREADS, smem>>>(h);
    conv_kernel<<<D_DIM * BSZ, THREADS, smem>>>(x, B, y);
}

// round 2
// speedup vs baseline: 1.7155x; 1.7155x over previous
#include <cuda_runtime.h>
#include <math.h>

#define N_FFT   16384
#define L_SIG   8192
#define D_DIM   1024
#define BSZ     4
#define THREADS 1024
#define NSTAGES 7   /* radix-4: 4^7 = 16384 */

// Scratch (allocation-free rule: __device__ globals)
__device__ float2 d_tw[N_FFT / 4];             // exp(-2*pi*i*k/N), k < N/4  (32 KB)
__device__ float2 d_Hf[(size_t)D_DIM * N_FFT]; // digit-reversed spectra of h rows (128 MB)

__device__ __forceinline__ float2 cmul(float2 a, float2 b) {
    return make_float2(a.x * b.x - a.y * b.y, a.x * b.y + a.y * b.x);
}

__global__ void twiddle_kernel() {
    int k = blockIdx.x * blockDim.x + threadIdx.x;
    if (k < N_FFT / 4) {
        double ang = -2.0 * 3.14159265358979323846 * (double)k / (double)N_FFT;
        d_tw[k] = make_float2((float)cos(ang), (float)sin(ang));
    }
}

// ---------------- radix-4 DIF forward: natural in -> base-4 digit-reversed out
__device__ __forceinline__ void fft_fwd(float2* s) {
    const int tid = threadIdx.x;
#pragma unroll
    for (int stage = 0; stage < NSTAGES; ++stage) {
        const int lq  = 12 - 2 * stage;       // log2(q), q = m/4, m = N >> 2*stage
        const int q   = 1 << lq;
        const int tws = 1 << (2 * stage);     // N/m
#pragma unroll
        for (int t = tid; t < (N_FFT >> 2); t += THREADS) {
            const int j    = t & (q - 1);
            const int base = (t >> lq) << (lq + 2);
            const int i0   = base + j;
            float2 a0 = s[i0], a1 = s[i0 + q], a2 = s[i0 + 2 * q], a3 = s[i0 + 3 * q];
            float2 t0 = make_float2(a0.x + a2.x, a0.y + a2.y);
            float2 t1 = make_float2(a0.x - a2.x, a0.y - a2.y);
            float2 t2 = make_float2(a1.x + a3.x, a1.y + a3.y);
            float2 t3 = make_float2(a1.x - a3.x, a1.y - a3.y);
            float2 b0 = make_float2(t0.x + t2.x, t0.y + t2.y);
            float2 b2 = make_float2(t0.x - t2.x, t0.y - t2.y);
            float2 b1 = make_float2(t1.x + t3.y, t1.y - t3.x);   // t1 - i*t3
            float2 b3 = make_float2(t1.x - t3.y, t1.y + t3.x);   // t1 + i*t3
            float2 w1 = d_tw[j * tws];
            float2 w2 = cmul(w1, w1);
            float2 w3 = cmul(w1, w2);
            s[i0]         = b0;
            s[i0 + q]     = cmul(b1, w1);
            s[i0 + 2 * q] = cmul(b2, w2);
            s[i0 + 3 * q] = cmul(b3, w3);
        }
        __syncthreads();
    }
}

// ---------------- radix-4 DIT inverse (conjugate-transpose of fft_fwd), no 1/N scale
__device__ __forceinline__ void fft_inv(float2* s) {
    const int tid = threadIdx.x;
#pragma unroll
    for (int stage = 0; stage < NSTAGES; ++stage) {
        const int lq  = 2 * stage;            // q = 4^stage, m = 4^(stage+1)
        const int q   = 1 << lq;
        const int tws = N_FFT >> (lq + 2);    // N/m
#pragma unroll
        for (int t = tid; t < (N_FFT >> 2); t += THREADS) {
            const int j    = t & (q - 1);
            const int base = (t >> lq) << (lq + 2);
            const int i0   = base + j;
            float2 c0 = s[i0], c1 = s[i0 + q], c2 = s[i0 + 2 * q], c3 = s[i0 + 3 * q];
            float2 w1 = d_tw[j * tws];
            w1.y = -w1.y;                     // conjugate for inverse
            float2 w2 = cmul(w1, w1);
            float2 w3 = cmul(w1, w2);
            float2 a1 = cmul(c1, w1);
            float2 a2 = cmul(c2, w2);
            float2 a3 = cmul(c3, w3);
            float2 u0 = make_float2(c0.x + a2.x, c0.y + a2.y);
            float2 u1 = make_float2(c0.x - a2.x, c0.y - a2.y);
            float2 u2 = make_float2(a1.x + a3.x, a1.y + a3.y);
            float2 u3 = make_float2(a1.x - a3.x, a1.y - a3.y);
            s[i0]         = make_float2(u0.x + u2.x, u0.y + u2.y);
            s[i0 + q]     = make_float2(u1.x - u3.y, u1.y + u3.x);  // u1 + i*u3
            s[i0 + 2 * q] = make_float2(u0.x - u2.x, u0.y - u2.y);
            s[i0 + 3 * q] = make_float2(u1.x + u3.y, u1.y - u3.x);  // u1 - i*u3
        }
        __syncthreads();
    }
}

// ---------------- per-row spectrum of h (recomputed every launch: determinism)
__global__ __launch_bounds__(THREADS, 1) void hfft_kernel(const float* __restrict__ h) {
    extern __shared__ float2 s[];
    const int d = blockIdx.x;
    const float* hr = h + (size_t)d * L_SIG;
    for (int i = threadIdx.x; i < L_SIG; i += THREADS)
        s[i] = make_float2(hr[i], 0.f);
    for (int i = L_SIG + threadIdx.x; i < N_FFT; i += THREADS)
        s[i] = make_float2(0.f, 0.f);
    __syncthreads();
    fft_fwd(s);
    float2* out = d_Hf + (size_t)d * N_FFT;
    for (int i = threadIdx.x; i < N_FFT; i += THREADS)
        out[i] = s[i];
}

// ---------------- FFT conv, batch-packed: one CTA handles (d, batch-pair p).
// z = x[b0] + i*x[b1]; IFFT(Hf*FFT(z)) = y[b0] + i*y[b1] by linearity (h real,
// same multiplier for both batches -> no Hermitian split needed).
__global__ __launch_bounds__(THREADS, 1) void conv_kernel(const float* __restrict__ x,
                                                          const float* __restrict__ Bp,
                                                          float* __restrict__ y) {
    extern __shared__ float2 s[];
    const int blk = blockIdx.x;
    const int d = blk >> 1;          // d-major: pair-siblings adjacent -> Hf L2 reuse
    const int p = blk & 1;           // batch pair: (0,1) or (2,3)
    const int b0 = 2 * p, b1 = 2 * p + 1;
    const float* xr0 = x + ((size_t)b0 * D_DIM + d) * L_SIG;
    const float* xr1 = x + ((size_t)b1 * D_DIM + d) * L_SIG;
    float* yr0       = y + ((size_t)b0 * D_DIM + d) * L_SIG;
    float* yr1       = y + ((size_t)b1 * D_DIM + d) * L_SIG;

    for (int i = threadIdx.x; i < L_SIG; i += THREADS)
        s[i] = make_float2(xr0[i], xr1[i]);
    for (int i = L_SIG + threadIdx.x; i < N_FFT; i += THREADS)
        s[i] = make_float2(0.f, 0.f);
    __syncthreads();

    fft_fwd(s);

    const float2* Hr = d_Hf + (size_t)d * N_FFT;
    const float scale = 1.0f / (float)N_FFT;
    for (int i = threadIdx.x; i < N_FFT; i += THREADS) {
        float2 pz = cmul(s[i], Hr[i]);
        s[i] = make_float2(pz.x * scale, pz.y * scale);
    }
    __syncthreads();

    fft_inv(s);

    const float Bv = Bp[d];
    for (int i = threadIdx.x; i < L_SIG; i += THREADS) {
        float2 v = s[i];
        yr0[i] = v.x + Bv * xr0[i];
        yr1[i] = v.y + Bv * xr1[i];
    }
}

extern "C" void kernel_launch(void* const* d_in, const int* in_sizes, int n_in,
                              void* d_out, int out_size) {
    const float* h = (const float*)d_in[0];
    const float* x = (const float*)d_in[1];
    const float* B = (const float*)d_in[2];
    float* y = (float*)d_out;

    const size_t smem = (size_t)N_FFT * sizeof(float2);  // 128 KB
    cudaFuncSetAttribute(hfft_kernel, cudaFuncAttributeMaxDynamicSharedMemorySize, (int)smem);
    cudaFuncSetAttribute(conv_kernel, cudaFuncAttributeMaxDynamicSharedMemorySize, (int)smem);

    twiddle_kernel<<<(N_FFT / 4 + 255) / 256, 256>>>();
    hfft_kernel<<<D_DIM, THREADS, smem>>>(h);
    conv_kernel<<<D_DIM * (BSZ / 2), THREADS, smem>>>(x, B, y);
}

// round 3
// speedup vs baseline: 3.1893x; 1.8592x over previous
#include <cuda_runtime.h>
#include <math.h>

#define N_FFT   16384
#define L_SIG   8192
#define D_DIM   1024
#define BSZ     4
#define THREADS 512

// XOR swizzle: kills smem bank conflicts for every stride used here (<=2-way).
#define SWZ(i) ((i) ^ (((i) >> 4) & 15))

__device__ float2 d_tw[N_FFT / 4];             // exp(-2*pi*i*k/N), k < N/4
__device__ float2 d_Hf[(size_t)D_DIM * N_FFT]; // digit-reversed spectra of h rows (128 MB)

__device__ __forceinline__ float2 cmul(float2 a, float2 b) {
    return make_float2(a.x * b.x - a.y * b.y, a.x * b.y + a.y * b.x);
}

__global__ void twiddle_kernel() {
    int k = blockIdx.x * blockDim.x + threadIdx.x;
    if (k < N_FFT / 4) {
        double ang = -2.0 * 3.14159265358979323846 * (double)k / (double)N_FFT;
        d_tw[k] = make_float2((float)cos(ang), (float)sin(ang));
    }
}

// DIF radix-4 butterfly, twiddles on outputs
__device__ __forceinline__ void dif4(float2& a0, float2& a1, float2& a2, float2& a3, float2 w1) {
    float2 t0 = make_float2(a0.x + a2.x, a0.y + a2.y);
    float2 t1 = make_float2(a0.x - a2.x, a0.y - a2.y);
    float2 t2 = make_float2(a1.x + a3.x, a1.y + a3.y);
    float2 t3 = make_float2(a1.x - a3.x, a1.y - a3.y);
    float2 b0 = make_float2(t0.x + t2.x, t0.y + t2.y);
    float2 b2 = make_float2(t0.x - t2.x, t0.y - t2.y);
    float2 b1 = make_float2(t1.x + t3.y, t1.y - t3.x);   // t1 - i*t3
    float2 b3 = make_float2(t1.x - t3.y, t1.y + t3.x);   // t1 + i*t3
    float2 w2 = cmul(w1, w1), w3 = cmul(w1, w2);
    a0 = b0; a1 = cmul(b1, w1); a2 = cmul(b2, w2); a3 = cmul(b3, w3);
}
__device__ __forceinline__ void dif4_nt(float2& a0, float2& a1, float2& a2, float2& a3) {
    float2 t0 = make_float2(a0.x + a2.x, a0.y + a2.y);
    float2 t1 = make_float2(a0.x - a2.x, a0.y - a2.y);
    float2 t2 = make_float2(a1.x + a3.x, a1.y + a3.y);
    float2 t3 = make_float2(a1.x - a3.x, a1.y - a3.y);
    a0 = make_float2(t0.x + t2.x, t0.y + t2.y);
    a2 = make_float2(t0.x - t2.x, t0.y - t2.y);
    a1 = make_float2(t1.x + t3.y, t1.y - t3.x);
    a3 = make_float2(t1.x - t3.y, t1.y + t3.x);
}

// DIT radix-4 inverse butterfly, (pre-conjugated) twiddles on inputs
__device__ __forceinline__ void dit4(float2& c0, float2& c1, float2& c2, float2& c3, float2 w1) {
    float2 w2 = cmul(w1, w1), w3 = cmul(w1, w2);
    float2 a1 = cmul(c1, w1), a2 = cmul(c2, w2), a3 = cmul(c3, w3);
    float2 u0 = make_float2(c0.x + a2.x, c0.y + a2.y);
    float2 u1 = make_float2(c0.x - a2.x, c0.y - a2.y);
    float2 u2 = make_float2(a1.x + a3.x, a1.y + a3.y);
    float2 u3 = make_float2(a1.x - a3.x, a1.y - a3.y);
    c0 = make_float2(u0.x + u2.x, u0.y + u2.y);
    c1 = make_float2(u1.x - u3.y, u1.y + u3.x);  // u1 + i*u3
    c2 = make_float2(u0.x - u2.x, u0.y - u2.y);
    c3 = make_float2(u1.x + u3.y, u1.y - u3.x);  // u1 - i*u3
}
__device__ __forceinline__ void dit4_nt(float2& c0, float2& c1, float2& c2, float2& c3) {
    float2 u0 = make_float2(c0.x + c2.x, c0.y + c2.y);
    float2 u1 = make_float2(c0.x - c2.x, c0.y - c2.y);
    float2 u2 = make_float2(c1.x + c3.x, c1.y + c3.y);
    float2 u3 = make_float2(c1.x - c3.x, c1.y - c3.y);
    c0 = make_float2(u0.x + u2.x, u0.y + u2.y);
    c1 = make_float2(u1.x - u3.y, u1.y + u3.x);
    c2 = make_float2(u0.x - u2.x, u0.y - u2.y);
    c3 = make_float2(u1.x + u3.y, u1.y - u3.x);
}

// Fused fwd stages (s, s+1): radix-16 pass. Q = q of the second stage.
template <int LQ>
__device__ __forceinline__ void fwd16_pass(float2* s) {
    const int Q = 1 << LQ;
    const int TWS1 = N_FFT >> (LQ + 4);   // first (larger-q) stage
    const int TWS2 = N_FFT >> (LQ + 2);   // second stage
#pragma unroll
    for (int gg = 0; gg < 2; ++gg) {
        const int G = threadIdx.x + gg * THREADS;
        const int j = G & (Q - 1);
        const int base = (G >> LQ) << (LQ + 4);
        float2 e[16];
#pragma unroll
        for (int u = 0; u < 16; ++u) e[u] = s[SWZ(base + j + (u << LQ))];
#pragma unroll
        for (int c = 0; c < 4; ++c) {
            float2 w1 = d_tw[(j + (c << LQ)) * TWS1];
            dif4(e[c], e[c + 4], e[c + 8], e[c + 12], w1);
        }
        float2 wB = d_tw[j * TWS2];
#pragma unroll
        for (int c = 0; c < 4; ++c)
            dif4(e[4 * c], e[4 * c + 1], e[4 * c + 2], e[4 * c + 3], wB);
#pragma unroll
        for (int u = 0; u < 16; ++u) s[SWZ(base + j + (u << LQ))] = e[u];
    }
}

// Fused inverse stages (t, t+1): radix-16 pass. Q = q of the first stage.
template <int LQ>
__device__ __forceinline__ void inv16_pass(float2* s) {
    const int Q = 1 << LQ;
    const int TWSA = N_FFT >> (LQ + 2);
    const int TWSB = N_FFT >> (LQ + 4);
#pragma unroll
    for (int gg = 0; gg < 2; ++gg) {
        const int G = threadIdx.x + gg * THREADS;
        const int j = G & (Q - 1);
        const int base = (G >> LQ) << (LQ + 4);
        float2 e[16];
#pragma unroll
        for (int u = 0; u < 16; ++u) e[u] = s[SWZ(base + j + (u << LQ))];
        float2 wA = d_tw[j * TWSA]; wA.y = -wA.y;
#pragma unroll
        for (int c = 0; c < 4; ++c)
            dit4(e[4 * c], e[4 * c + 1], e[4 * c + 2], e[4 * c + 3], wA);
#pragma unroll
        for (int c = 0; c < 4; ++c) {
            float2 wB = d_tw[(j + (c << LQ)) * TWSB]; wB.y = -wB.y;
            dit4(e[c], e[c + 4], e[c + 8], e[c + 12], wB);
        }
#pragma unroll
        for (int u = 0; u < 16; ++u) s[SWZ(base + j + (u << LQ))] = e[u];
    }
}

// fwd stages 5 (q=4, twiddle c*1024) and 6 (q=1, twiddle-free) on 16 consecutive elems
__device__ __forceinline__ void fwd_tail(float2 e[16]) {
#pragma unroll
    for (int c = 0; c < 4; ++c) {
        float2 w = d_tw[c << 10];
        dif4(e[c], e[c + 4], e[c + 8], e[c + 12], w);
    }
#pragma unroll
    for (int c = 0; c < 4; ++c)
        dif4_nt(e[4 * c], e[4 * c + 1], e[4 * c + 2], e[4 * c + 3]);
}
// inverse stages 0 (twiddle-free) and 1 (q=4, conj twiddle c*1024)
__device__ __forceinline__ void inv_head(float2 e[16]) {
#pragma unroll
    for (int c = 0; c < 4; ++c)
        dit4_nt(e[4 * c], e[4 * c + 1], e[4 * c + 2], e[4 * c + 3]);
#pragma unroll
    for (int c = 0; c < 4; ++c) {
        float2 w = d_tw[c << 10]; w.y = -w.y;
        dit4(e[c], e[c + 4], e[c + 8], e[c + 12], w);
    }
}

// ---------------- h spectrum: P0(global) | fwd16 | fwd16 | tail + global store
__global__ __launch_bounds__(THREADS, 1) void hfft_kernel(const float* __restrict__ h) {
    extern __shared__ float2 s[];
    const int d = blockIdx.x;
    const float* hr = h + (size_t)d * L_SIG;
    const int tid = threadIdx.x;

    // fwd stage 0 (q=4096), inputs c2=c3=0 (zero padding)
#pragma unroll
    for (int k = 0; k < 8; ++k) {
        int j = tid + THREADS * k;
        float2 a0 = make_float2(hr[j], 0.f);
        float2 a1 = make_float2(hr[j + 4096], 0.f);
        float2 b0 = make_float2(a0.x + a1.x, a0.y + a1.y);
        float2 b2 = make_float2(a0.x - a1.x, a0.y - a1.y);
        float2 b1 = make_float2(a0.x + a1.y, a0.y - a1.x);  // a0 - i*a1
        float2 b3 = make_float2(a0.x - a1.y, a0.y + a1.x);  // a0 + i*a1
        float2 w1 = d_tw[j];
        float2 w2 = cmul(w1, w1), w3 = cmul(w1, w2);
        s[SWZ(j)]         = b0;
        s[SWZ(j + 4096)]  = cmul(b1, w1);
        s[SWZ(j + 8192)]  = cmul(b2, w2);
        s[SWZ(j + 12288)] = cmul(b3, w3);
    }
    __syncthreads();
    fwd16_pass<8>(s);   // stages 1,2
    __syncthreads();
    fwd16_pass<4>(s);   // stages 3,4
    __syncthreads();
    // stages 5,6 + store digit-reversed spectrum to global (sector-coalesced)
    float4* out4 = reinterpret_cast<float4*>(d_Hf + (size_t)d * N_FFT);
#pragma unroll
    for (int gg = 0; gg < 2; ++gg) {
        const int G = tid + THREADS * gg;
        const int base = G << 4;
        const int r = G & 15;
        float2 e[16];
#pragma unroll
        for (int u = 0; u < 16; ++u) e[u] = s[base + (u ^ r)];
        fwd_tail(e);
#pragma unroll
        for (int v = 0; v < 8; ++v)
            out4[(base >> 1) + v] = make_float4(e[2 * v].x, e[2 * v].y,
                                                e[2 * v + 1].x, e[2 * v + 1].y);
    }
}

// ---------------- conv: batch-packed (z = x[b0] + i*x[b1]), 7 passes total
__global__ __launch_bounds__(THREADS, 1) void conv_kernel(const float* __restrict__ x,
                                                          const float* __restrict__ Bp,
                                                          float* __restrict__ y) {
    extern __shared__ float2 s[];
    const int blk = blockIdx.x;
    const int d = blk >> 1;          // d-major: pair-siblings adjacent -> Hf L2 reuse
    const int p = blk & 1;
    const float* x0 = x + ((size_t)(2 * p) * D_DIM + d) * L_SIG;
    const float* x1 = x + ((size_t)(2 * p + 1) * D_DIM + d) * L_SIG;
    float* y0       = y + ((size_t)(2 * p) * D_DIM + d) * L_SIG;
    float* y1       = y + ((size_t)(2 * p + 1) * D_DIM + d) * L_SIG;
    const int tid = threadIdx.x;

    // P0: fwd stage 0 straight from global, zero-padded upper half
#pragma unroll
    for (int k = 0; k < 8; ++k) {
        int j = tid + THREADS * k;
        float2 a0 = make_float2(x0[j], x1[j]);
        float2 a1 = make_float2(x0[j + 4096], x1[j + 4096]);
        float2 b0 = make_float2(a0.x + a1.x, a0.y + a1.y);
        float2 b2 = make_float2(a0.x - a1.x, a0.y - a1.y);
        float2 b1 = make_float2(a0.x + a1.y, a0.y - a1.x);
        float2 b3 = make_float2(a0.x - a1.y, a0.y + a1.x);
        float2 w1 = d_tw[j];
        float2 w2 = cmul(w1, w1), w3 = cmul(w1, w2);
        s[SWZ(j)]         = b0;
        s[SWZ(j + 4096)]  = cmul(b1, w1);
        s[SWZ(j + 8192)]  = cmul(b2, w2);
        s[SWZ(j + 12288)] = cmul(b3, w3);
    }
    __syncthreads();
    fwd16_pass<8>(s);   // fwd stages 1,2
    __syncthreads();
    fwd16_pass<4>(s);   // fwd stages 3,4
    __syncthreads();

    // P3: fwd stages 5,6 + pointwise Hf/N + inv stages 0,1 — one smem round trip
    const float4* H4 = reinterpret_cast<const float4*>(d_Hf + (size_t)d * N_FFT);
    const float scale = 1.0f / (float)N_FFT;
#pragma unroll
    for (int gg = 0; gg < 2; ++gg) {
        const int G = tid + THREADS * gg;
        const int base = G << 4;
        const int r = G & 15;
        float2 e[16];
#pragma unroll
        for (int u = 0; u < 16; ++u) e[u] = s[base + (u ^ r)];
        fwd_tail(e);
#pragma unroll
        for (int v = 0; v < 8; ++v) {
            float4 hv = H4[(base >> 1) + v];
            float2 p0 = cmul(e[2 * v],     make_float2(hv.x, hv.y));
            float2 p1 = cmul(e[2 * v + 1], make_float2(hv.z, hv.w));
            e[2 * v]     = make_float2(p0.x * scale, p0.y * scale);
            e[2 * v + 1] = make_float2(p1.x * scale, p1.y * scale);
        }
        inv_head(e);
#pragma unroll
        for (int u = 0; u < 16; ++u) s[base + (u ^ r)] = e[u];
    }
    __syncthreads();
    inv16_pass<4>(s);   // inv stages 2,3
    __syncthreads();
    inv16_pass<8>(s);   // inv stages 4,5
    __syncthreads();

    // P6: inv stage 6 (q=4096) + write y (+ B*x), skip stores of upper garbage half
    const float Bv = Bp[d];
#pragma unroll
    for (int k = 0; k < 8; ++k) {
        int j = tid + THREADS * k;
        float2 c0 = s[SWZ(j)];
        float2 c1 = s[SWZ(j + 4096)];
        float2 c2 = s[SWZ(j + 8192)];
        float2 c3 = s[SWZ(j + 12288)];
        float2 w1 = d_tw[j]; w1.y = -w1.y;
        dit4(c0, c1, c2, c3, w1);
        y0[j]        = c0.x + Bv * x0[j];
        y1[j]        = c0.y + Bv * x1[j];
        y0[j + 4096] = c1.x + Bv * x0[j + 4096];
        y1[j + 4096] = c1.y + Bv * x1[j + 4096];
    }
}

extern "C" void kernel_launch(void* const* d_in, const int* in_sizes, int n_in,
                              void* d_out, int out_size) {
    const float* h = (const float*)d_in[0];
    const float* x = (const float*)d_in[1];
    const float* B = (const float*)d_in[2];
    float* y = (float*)d_out;

    const size_t smem = (size_t)N_FFT * sizeof(float2);  // 128 KB
    cudaFuncSetAttribute(hfft_kernel, cudaFuncAttributeMaxDynamicSharedMemorySize, (int)smem);
    cudaFuncSetAttribute(conv_kernel, cudaFuncAttributeMaxDynamicSharedMemorySize, (int)smem);

    twiddle_kernel<<<(N_FFT / 4 + 255) / 256, 256>>>();
    hfft_kernel<<<D_DIM, THREADS, smem>>>(h);
    conv_kernel<<<D_DIM * (BSZ / 2), THREADS, smem>>>(x, B, y);
}

// round 4
// speedup vs baseline: 3.3041x; 1.0360x over previous
#include <cuda_runtime.h>
#include <math.h>

#define N_FFT   16384
#define L_SIG   8192
#define D_DIM   1024
#define BSZ     4
#define THREADS 512

// XOR swizzle: kills smem bank conflicts for every stride used here (<=2-way).
#define SWZ(i) ((i) ^ (((i) >> 4) & 15))

__device__ float2 d_tw[N_FFT / 4];             // exp(-2*pi*i*k/N), k < N/4
__device__ float2 d_Hf[(size_t)D_DIM * N_FFT]; // digit-reversed spectra of (h + B*delta0) rows
__device__ unsigned d_flags[D_DIM];            // per-row ready flags (reset each launch)

__device__ __forceinline__ float2 cmul(float2 a, float2 b) {
    return make_float2(a.x * b.x - a.y * b.y, a.x * b.y + a.y * b.x);
}

// Init: twiddle table + flag reset (runs at the head of every launch)
__global__ void init_kernel() {
    int k = blockIdx.x * blockDim.x + threadIdx.x;
    if (k < N_FFT / 4) {
        double ang = -2.0 * 3.14159265358979323846 * (double)k / (double)N_FFT;
        d_tw[k] = make_float2((float)cos(ang), (float)sin(ang));
    }
    if (k < D_DIM) d_flags[k] = 0u;
}

// DIF radix-4 butterfly, twiddles on outputs
__device__ __forceinline__ void dif4(float2& a0, float2& a1, float2& a2, float2& a3, float2 w1) {
    float2 t0 = make_float2(a0.x + a2.x, a0.y + a2.y);
    float2 t1 = make_float2(a0.x - a2.x, a0.y - a2.y);
    float2 t2 = make_float2(a1.x + a3.x, a1.y + a3.y);
    float2 t3 = make_float2(a1.x - a3.x, a1.y - a3.y);
    float2 b0 = make_float2(t0.x + t2.x, t0.y + t2.y);
    float2 b2 = make_float2(t0.x - t2.x, t0.y - t2.y);
    float2 b1 = make_float2(t1.x + t3.y, t1.y - t3.x);   // t1 - i*t3
    float2 b3 = make_float2(t1.x - t3.y, t1.y + t3.x);   // t1 + i*t3
    float2 w2 = cmul(w1, w1), w3 = cmul(w1, w2);
    a0 = b0; a1 = cmul(b1, w1); a2 = cmul(b2, w2); a3 = cmul(b3, w3);
}
__device__ __forceinline__ void dif4_nt(float2& a0, float2& a1, float2& a2, float2& a3) {
    float2 t0 = make_float2(a0.x + a2.x, a0.y + a2.y);
    float2 t1 = make_float2(a0.x - a2.x, a0.y - a2.y);
    float2 t2 = make_float2(a1.x + a3.x, a1.y + a3.y);
    float2 t3 = make_float2(a1.x - a3.x, a1.y - a3.y);
    a0 = make_float2(t0.x + t2.x, t0.y + t2.y);
    a2 = make_float2(t0.x - t2.x, t0.y - t2.y);
    a1 = make_float2(t1.x + t3.y, t1.y - t3.x);
    a3 = make_float2(t1.x - t3.y, t1.y + t3.x);
}

// DIT radix-4 inverse butterfly, (pre-conjugated) twiddles on inputs
__device__ __forceinline__ void dit4(float2& c0, float2& c1, float2& c2, float2& c3, float2 w1) {
    float2 w2 = cmul(w1, w1), w3 = cmul(w1, w2);
    float2 a1 = cmul(c1, w1), a2 = cmul(c2, w2), a3 = cmul(c3, w3);
    float2 u0 = make_float2(c0.x + a2.x, c0.y + a2.y);
    float2 u1 = make_float2(c0.x - a2.x, c0.y - a2.y);
    float2 u2 = make_float2(a1.x + a3.x, a1.y + a3.y);
    float2 u3 = make_float2(a1.x - a3.x, a1.y - a3.y);
    c0 = make_float2(u0.x + u2.x, u0.y + u2.y);
    c1 = make_float2(u1.x - u3.y, u1.y + u3.x);  // u1 + i*u3
    c2 = make_float2(u0.x - u2.x, u0.y - u2.y);
    c3 = make_float2(u1.x + u3.y, u1.y - u3.x);  // u1 - i*u3
}
__device__ __forceinline__ void dit4_nt(float2& c0, float2& c1, float2& c2, float2& c3) {
    float2 u0 = make_float2(c0.x + c2.x, c0.y + c2.y);
    float2 u1 = make_float2(c0.x - c2.x, c0.y - c2.y);
    float2 u2 = make_float2(c1.x + c3.x, c1.y + c3.y);
    float2 u3 = make_float2(c1.x - c3.x, c1.y - c3.y);
    c0 = make_float2(u0.x + u2.x, u0.y + u2.y);
    c1 = make_float2(u1.x - u3.y, u1.y + u3.x);
    c2 = make_float2(u0.x - u2.x, u0.y - u2.y);
    c3 = make_float2(u1.x + u3.y, u1.y - u3.x);
}

// Fused fwd stages (s, s+1): radix-16 pass.
template <int LQ>
__device__ __forceinline__ void fwd16_pass(float2* s) {
    const int Q = 1 << LQ;
    const int TWS1 = N_FFT >> (LQ + 4);
    const int TWS2 = N_FFT >> (LQ + 2);
#pragma unroll
    for (int gg = 0; gg < 2; ++gg) {
        const int G = threadIdx.x + gg * THREADS;
        const int j = G & (Q - 1);
        const int base = (G >> LQ) << (LQ + 4);
        float2 e[16];
#pragma unroll
        for (int u = 0; u < 16; ++u) e[u] = s[SWZ(base + j + (u << LQ))];
#pragma unroll
        for (int c = 0; c < 4; ++c) {
            float2 w1 = d_tw[(j + (c << LQ)) * TWS1];
            dif4(e[c], e[c + 4], e[c + 8], e[c + 12], w1);
        }
        float2 wB = d_tw[j * TWS2];
#pragma unroll
        for (int c = 0; c < 4; ++c)
            dif4(e[4 * c], e[4 * c + 1], e[4 * c + 2], e[4 * c + 3], wB);
#pragma unroll
        for (int u = 0; u < 16; ++u) s[SWZ(base + j + (u << LQ))] = e[u];
    }
}

// Fused inverse stages (t, t+1): radix-16 pass.
template <int LQ>
__device__ __forceinline__ void inv16_pass(float2* s) {
    const int Q = 1 << LQ;
    const int TWSA = N_FFT >> (LQ + 2);
    const int TWSB = N_FFT >> (LQ + 4);
#pragma unroll
    for (int gg = 0; gg < 2; ++gg) {
        const int G = threadIdx.x + gg * THREADS;
        const int j = G & (Q - 1);
        const int base = (G >> LQ) << (LQ + 4);
        float2 e[16];
#pragma unroll
        for (int u = 0; u < 16; ++u) e[u] = s[SWZ(base + j + (u << LQ))];
        float2 wA = d_tw[j * TWSA]; wA.y = -wA.y;
#pragma unroll
        for (int c = 0; c < 4; ++c)
            dit4(e[4 * c], e[4 * c + 1], e[4 * c + 2], e[4 * c + 3], wA);
#pragma unroll
        for (int c = 0; c < 4; ++c) {
            float2 wB = d_tw[(j + (c << LQ)) * TWSB]; wB.y = -wB.y;
            dit4(e[c], e[c + 4], e[c + 8], e[c + 12], wB);
        }
#pragma unroll
        for (int u = 0; u < 16; ++u) s[SWZ(base + j + (u << LQ))] = e[u];
    }
}

// fwd stages 5 (q=4) and 6 (q=1, twiddle-free) on 16 consecutive elems
__device__ __forceinline__ void fwd_tail(float2 e[16]) {
#pragma unroll
    for (int c = 0; c < 4; ++c) {
        float2 w = d_tw[c << 10];
        dif4(e[c], e[c + 4], e[c + 8], e[c + 12], w);
    }
#pragma unroll
    for (int c = 0; c < 4; ++c)
        dif4_nt(e[4 * c], e[4 * c + 1], e[4 * c + 2], e[4 * c + 3]);
}
// inverse stages 0 (twiddle-free) and 1 (q=4)
__device__ __forceinline__ void inv_head(float2 e[16]) {
#pragma unroll
    for (int c = 0; c < 4; ++c)
        dit4_nt(e[4 * c], e[4 * c + 1], e[4 * c + 2], e[4 * c + 3]);
#pragma unroll
    for (int c = 0; c < 4; ++c) {
        float2 w = d_tw[c << 10]; w.y = -w.y;
        dit4(e[c], e[c + 4], e[c + 8], e[c + 12], w);
    }
}

// ---------------- fused kernel: bids [0,1024) produce Hf rows; [1024,3072) consume
__global__ __launch_bounds__(THREADS, 1) void fftconv_kernel(const float* __restrict__ h,
                                                             const float* __restrict__ x,
                                                             const float* __restrict__ Bp,
                                                             float* __restrict__ y) {
    extern __shared__ float2 s[];
    const int bid = blockIdx.x;
    const int tid = threadIdx.x;

    if (bid < D_DIM) {
        // ================= producer: spectrum of h_eff = h + B*delta0 =================
        const int d = bid;
        const float* hr = h + (size_t)d * L_SIG;
        const float Bv = Bp[d];
        // fwd stage 0 (q=4096), upper half zero-padded
#pragma unroll
        for (int k = 0; k < 8; ++k) {
            int j = tid + THREADS * k;
            float a0r = hr[j] + ((j == 0) ? Bv : 0.f);   // fold B*x into spectrum
            float a1r = hr[j + 4096];
            float2 b0 = make_float2(a0r + a1r, 0.f);
            float2 b2 = make_float2(a0r - a1r, 0.f);
            float2 b1 = make_float2(a0r, -a1r);          // a0 - i*a1 (real inputs)
            float2 b3 = make_float2(a0r,  a1r);          // a0 + i*a1
            float2 w1 = d_tw[j];
            float2 w2 = cmul(w1, w1), w3 = cmul(w1, w2);
            s[SWZ(j)]         = b0;
            s[SWZ(j + 4096)]  = cmul(b1, w1);
            s[SWZ(j + 8192)]  = cmul(b2, w2);
            s[SWZ(j + 12288)] = cmul(b3, w3);
        }
        __syncthreads();
        fwd16_pass<8>(s);
        __syncthreads();
        fwd16_pass<4>(s);
        __syncthreads();
        float4* out4 = reinterpret_cast<float4*>(d_Hf + (size_t)d * N_FFT);
#pragma unroll
        for (int gg = 0; gg < 2; ++gg) {
            const int G = tid + THREADS * gg;
            const int base = G << 4;
            const int r = G & 15;
            float2 e[16];
#pragma unroll
            for (int u = 0; u < 16; ++u) e[u] = s[base + (u ^ r)];
            fwd_tail(e);
#pragma unroll
            for (int v = 0; v < 8; ++v)
                out4[(base >> 1) + v] = make_float4(e[2 * v].x, e[2 * v].y,
                                                    e[2 * v + 1].x, e[2 * v + 1].y);
        }
        __syncthreads();          // all Hf stores issued
        if (tid == 0) {
            __threadfence();      // release
            atomicExch(&d_flags[d], 1u);
        }
    } else {
        // ================= consumer: batch-packed conv =================
        const int c = bid - D_DIM;
        const int d = c >> 1;       // pair-siblings adjacent -> Hf L2 reuse
        const int p = c & 1;
        const float* x0 = x + ((size_t)(2 * p) * D_DIM + d) * L_SIG;
        const float* x1 = x + ((size_t)(2 * p + 1) * D_DIM + d) * L_SIG;
        float* y0       = y + ((size_t)(2 * p) * D_DIM + d) * L_SIG;
        float* y1       = y + ((size_t)(2 * p + 1) * D_DIM + d) * L_SIG;

        // P0: fwd stage 0 straight from global (z = x0 + i*x1), zero-padded
#pragma unroll
        for (int k = 0; k < 8; ++k) {
            int j = tid + THREADS * k;
            float2 a0 = make_float2(x0[j], x1[j]);
            float2 a1 = make_float2(x0[j + 4096], x1[j + 4096]);
            float2 b0 = make_float2(a0.x + a1.x, a0.y + a1.y);
            float2 b2 = make_float2(a0.x - a1.x, a0.y - a1.y);
            float2 b1 = make_float2(a0.x + a1.y, a0.y - a1.x);
            float2 b3 = make_float2(a0.x - a1.y, a0.y + a1.x);
            float2 w1 = d_tw[j];
            float2 w2 = cmul(w1, w1), w3 = cmul(w1, w2);
            s[SWZ(j)]         = b0;
            s[SWZ(j + 4096)]  = cmul(b1, w1);
            s[SWZ(j + 8192)]  = cmul(b2, w2);
            s[SWZ(j + 12288)] = cmul(b3, w3);
        }
        __syncthreads();
        fwd16_pass<8>(s);
        __syncthreads();
        fwd16_pass<4>(s);

        // Wait for Hf row d (producers have strictly lower bids -> guaranteed progress)
        if (tid == 0) {
            while (atomicAdd(&d_flags[d], 0u) == 0u) __nanosleep(64);
        }
        __syncthreads();
        __threadfence();          // acquire for Hf reads below

        // P3: fwd stages 5,6 + pointwise Hf/N + inv stages 0,1
        const float4* H4 = reinterpret_cast<const float4*>(d_Hf + (size_t)d * N_FFT);
        const float scale = 1.0f / (float)N_FFT;
#pragma unroll
        for (int gg = 0; gg < 2; ++gg) {
            const int G = tid + THREADS * gg;
            const int base = G << 4;
            const int r = G & 15;
            float4 hv[8];
#pragma unroll
            for (int v = 0; v < 8; ++v) hv[v] = H4[(base >> 1) + v];  // prefetch
            float2 e[16];
#pragma unroll
            for (int u = 0; u < 16; ++u) e[u] = s[base + (u ^ r)];
            fwd_tail(e);
#pragma unroll
            for (int v = 0; v < 8; ++v) {
                float2 p0 = cmul(e[2 * v],     make_float2(hv[v].x, hv[v].y));
                float2 p1 = cmul(e[2 * v + 1], make_float2(hv[v].z, hv[v].w));
                e[2 * v]     = make_float2(p0.x * scale, p0.y * scale);
                e[2 * v + 1] = make_float2(p1.x * scale, p1.y * scale);
            }
            inv_head(e);
#pragma unroll
            for (int u = 0; u < 16; ++u) s[base + (u ^ r)] = e[u];
        }
        __syncthreads();
        inv16_pass<4>(s);
        __syncthreads();
        inv16_pass<8>(s);
        __syncthreads();

        // P6: inv stage 6 + direct y store (B*x already folded into Hf)
#pragma unroll
        for (int k = 0; k < 8; ++k) {
            int j = tid + THREADS * k;
            float2 c0 = s[SWZ(j)];
            float2 c1 = s[SWZ(j + 4096)];
            float2 c2 = s[SWZ(j + 8192)];
            float2 c3 = s[SWZ(j + 12288)];
            float2 w1 = d_tw[j]; w1.y = -w1.y;
            dit4(c0, c1, c2, c3, w1);
            y0[j]        = c0.x;
            y1[j]        = c0.y;
            y0[j + 4096] = c1.x;
            y1[j + 4096] = c1.y;
        }
    }
}

extern "C" void kernel_launch(void* const* d_in, const int* in_sizes, int n_in,
                              void* d_out, int out_size) {
    const float* h = (const float*)d_in[0];
    const float* x = (const float*)d_in[1];
    const float* B = (const float*)d_in[2];
    float* y = (float*)d_out;

    const size_t smem = (size_t)N_FFT * sizeof(float2);  // 128 KB
    cudaFuncSetAttribute(fftconv_kernel, cudaFuncAttributeMaxDynamicSharedMemorySize, (int)smem);

    init_kernel<<<16, 256>>>();
    fftconv_kernel<<<D_DIM + D_DIM * (BSZ / 2), THREADS, smem>>>(h, x, B, y);
}